// round 13
// baseline (speedup 1.0000x reference)
#include <cuda_runtime.h>
#include <cstdint>

#define SPATIAL 131072   // D*H*W per (batch, channel)
#define HW2     16384    // H*W
#define TW      136      // mid tile row stride (floats)

// Scratch (no allocations allowed anywhere)
__device__ float g_h [2 * 64 * SPATIAL];
__device__ float g_uv[2 * 64 * SPATIAL];
__device__ float g_vp[2 * 3  * SPATIAL];
__device__ float g_wt[2 * 4096];          // pre-transposed weights [k][m]

typedef unsigned long long u64;

__device__ __forceinline__ u64 pack_dup(float x) {
    u64 u; asm("mov.b64 %0, {%1, %2};" : "=l"(u) : "f"(x), "f"(x)); return u;
}
__device__ __forceinline__ u64 pack2(float a, float b) {
    u64 u; asm("mov.b64 %0, {%1, %2};" : "=l"(u) : "f"(a), "f"(b)); return u;
}
__device__ __forceinline__ void fma2(u64& d, u64 a, u64 b) {
    asm("fma.rn.f32x2 %0, %1, %2, %0;" : "+l"(d) : "l"(a), "l"(b));
}
__device__ __forceinline__ float2 unpk(u64 v) {
    float2 f; asm("mov.b64 {%0, %1}, %2;" : "=f"(f.x), "=f"(f.y) : "l"(v)); return f;
}
__device__ __forceinline__ uint32_t smem_u32(const void* p) {
    uint32_t a;
    asm("{ .reg .u64 t; cvta.to.shared.u64 t, %1; cvt.u32.u64 %0, t; }" : "=r"(a) : "l"(p));
    return a;
}
__device__ __forceinline__ void cpa4(uint32_t s, const void* g) {
    asm volatile("cp.async.ca.shared.global [%0], [%1], 4;" :: "r"(s), "l"(g) : "memory");
}

// ---------------------------------------------------------------------------
// One-time weight transpose: g_wt[sel][k*64+m] = W_sel[m*64+k]. 1 CTA.
// ---------------------------------------------------------------------------
__global__ void wtranspose(const float* __restrict__ hw,
                           const float* __restrict__ tw) {
    const int t = threadIdx.x;
#pragma unroll
    for (int i = 0; i < 16; ++i) {
        int idx = t + 256 * i;            // 0..4095
        int m = idx >> 6, k = idx & 63;
        g_wt[k * 64 + m]        = hw[idx];
        g_wt[4096 + k * 64 + m] = tw[idx];
    }
}

// ---------------------------------------------------------------------------
// f32x2 GEMM (R12, UNCHANGED — passed): C[b][m][p] = sum_k A[m][k]*X[b][k][p]
// CTA tile 64 x 128, 256 threads, thread tile 8m x 4n, 4 CTAs/SM.
// ---------------------------------------------------------------------------
template<bool VP_EPI>
__device__ __forceinline__ void gemm_body(const float* __restrict__ X,
                                          const float* __restrict__ WT,
                                          float* __restrict__ C,
                                          const float* __restrict__ Vw) {
    __shared__ float As[64 * 64];    // [k][m], linear copy of WT
    __shared__ float Bs[64 * 128];   // [k][c]
    const int t  = threadIdx.x;
    const int b  = blockIdx.y;
    const int p0 = blockIdx.x * 128;
    const float* Xb = X + b * (64 * SPATIAL);

#pragma unroll
    for (int i = 0; i < 4; ++i) {            // A: straight 16KB copy
        int u = t + 256 * i;
        *reinterpret_cast<float4*>(As + u * 4) =
            *reinterpret_cast<const float4*>(WT + u * 4);
    }
#pragma unroll
    for (int i = 0; i < 8; ++i) {            // B tile 64 x 128 (2048 float4)
        int fl = t + 256 * i;
        int k = fl >> 5, cq = fl & 31;
        *reinterpret_cast<float4*>(Bs + k * 128 + cq * 4) =
            *reinterpret_cast<const float4*>(Xb + k * SPATIAL + p0 + cq * 4);
    }
    __syncthreads();

    const int cg = t & 31;      // cols cg*4 .. cg*4+3
    const int rg = t >> 5;      // rows rg*8 .. rg*8+7
    u64 acc[16];
#pragma unroll
    for (int i = 0; i < 16; ++i) acc[i] = 0ull;

#pragma unroll 8
    for (int k = 0; k < 64; ++k) {
        float4 a0 = *reinterpret_cast<const float4*>(As + k * 64 + rg * 8);
        float4 a1 = *reinterpret_cast<const float4*>(As + k * 64 + rg * 8 + 4);
        float4 bv = *reinterpret_cast<const float4*>(Bs + k * 128 + cg * 4);
        u64 bp0 = pack2(bv.x, bv.y), bp1 = pack2(bv.z, bv.w);
        float am[8] = {a0.x, a0.y, a0.z, a0.w, a1.x, a1.y, a1.z, a1.w};
#pragma unroll
        for (int j = 0; j < 8; ++j) {
            u64 aj = pack_dup(am[j]);
            fma2(acc[j * 2 + 0], aj, bp0);
            fma2(acc[j * 2 + 1], aj, bp1);
        }
    }

    float* Cb = C + b * (64 * SPATIAL);
#pragma unroll
    for (int j = 0; j < 8; ++j) {
        float2 lo = unpk(acc[j * 2 + 0]), hi = unpk(acc[j * 2 + 1]);
        *reinterpret_cast<float4*>(Cb + (rg * 8 + j) * SPATIAL + p0 + cg * 4)
            = make_float4(lo.x, lo.y, hi.x, hi.y);
    }

    if (VP_EPI) {
        u64 pvp[3][2];
#pragma unroll
        for (int r = 0; r < 3; ++r) { pvp[r][0] = 0ull; pvp[r][1] = 0ull; }
#pragma unroll
        for (int j = 0; j < 8; ++j) {
            int m = rg * 8 + j;
#pragma unroll
            for (int r = 0; r < 3; ++r) {
                u64 vw = pack_dup(__ldg(&Vw[m * 3 + r]));
                fma2(pvp[r][0], vw, acc[j * 2 + 0]);
                fma2(pvp[r][1], vw, acc[j * 2 + 1]);
            }
        }
        __syncthreads();                      // Bs reads done -> reuse as vred
        float* vred = Bs;                     // [rowg 8][r 3][col 128] = 12KB
#pragma unroll
        for (int r = 0; r < 3; ++r) {
            *reinterpret_cast<float2*>(vred + (rg * 3 + r) * 128 + cg * 4)     = unpk(pvp[r][0]);
            *reinterpret_cast<float2*>(vred + (rg * 3 + r) * 128 + cg * 4 + 2) = unpk(pvp[r][1]);
        }
        __syncthreads();
#pragma unroll
        for (int i = 0; i < 2; ++i) {
            int idx = t + 256 * i;            // 384 outputs
            if (idx < 384) {
                int r = idx >> 7, col = idx & 127;
                float s = 0.f;
#pragma unroll
                for (int g = 0; g < 8; ++g) s += vred[(g * 3 + r) * 128 + col];
                g_vp[(b * 3 + r) * SPATIAL + p0 + col] = s;
            }
        }
    }
}

// Non-templated entry points (templated __global__ silently no-ops under harness)
__global__ void __launch_bounds__(256, 4)
gemm_head(const float* __restrict__ X, const float* __restrict__ Vw) {
    gemm_body<true>(X, g_wt, g_h, Vw);
}
__global__ void __launch_bounds__(256, 4)
gemm_tail(float* __restrict__ C) {
    gemm_body<false>(g_uv, g_wt + 4096, C, nullptr);
}

// ---------------------------------------------------------------------------
// Fused middle, pipelined: replicate-pad + depthwise 3x3x3 (3 ranks) +
// L2 norm + UV with precomputed Vp.
// CTA = 1 channel x all 8 d x 128 w; loops over 4 h-tiles of 4 rows with
// cp.async double-buffered halo staging (load s+1 overlaps compute s).
// 512 threads, 2 CTAs/SM. Compute mapping identical to the R7-passed mid.
// ---------------------------------------------------------------------------
__global__ void __launch_bounds__(512, 2) midkernel(const float* __restrict__ Uw) {
    __shared__ __align__(16) float tile[2][48 * TW];   // [buf][dz*6+hy][j], j=w+1
    __shared__ u64 uws2[81];
    const int t   = threadIdx.x;
    const int hb0 = blockIdx.x * 16;        // 16 h-rows per CTA (4 tiles of 4)
    const int c   = blockIdx.y;
    const int b   = blockIdx.z;
    const float* Hc = g_h + (b * 64 + c) * SPATIAL;

    if (t < 81) uws2[t] = pack_dup(Uw[t]);

    const int lwarp = t >> 5, lane = t & 31;

    // halo loader for tile starting at h-row h0s into buffer bi (cp.async)
#define ISSUE_LOAD(BI, H0S)                                                  \
    {                                                                        \
        _Pragma("unroll")                                                    \
        for (int rr = 0; rr < 3; ++rr) {                                     \
            int row = lwarp + rr * 16;           /* 0..47 */                 \
            int dz = row / 6, hy = row - dz * 6;                             \
            int gh = min(max((H0S) + hy - 1, 0), 127);                       \
            const float* src = Hc + dz * HW2 + gh * 128;                     \
            float* dst = &tile[BI][row * TW];                                \
            _Pragma("unroll")                                                \
            for (int q = 0; q < 5; ++q) {                                    \
                int j = lane + q * 32;                                       \
                if (j < 130)                                                 \
                    cpa4(smem_u32(dst + j), src + min(max(j - 1, 0), 127));  \
            }                                                                \
        }                                                                    \
        asm volatile("cp.async.commit_group;" ::: "memory");                 \
    }

    const int d  = t >> 6;          // 0..7
    const int wp = t & 63;
    const int w  = wp * 2;          // output pair; tile j=w holds in[w-1]
    const int zb0 = max(d - 1, 0) * 6;
    const int zb1 = d * 6;
    const int zb2 = min(d + 1, 7) * 6;

    float* UVc = g_uv + (b * 64 + c) * SPATIAL;
    const float* vpb0 = g_vp + (b * 3 + 0) * SPATIAL;
    const float* vpb1 = g_vp + (b * 3 + 1) * SPATIAL;
    const float* vpb2 = g_vp + (b * 3 + 2) * SPATIAL;

    ISSUE_LOAD(0, hb0);             // prologue: tile 0 -> buf 0

#pragma unroll
    for (int step = 0; step < 4; ++step) {
        const int h0s = hb0 + step * 4;
        if (step < 3) {
            ISSUE_LOAD((step + 1) & 1, h0s + 4);
            asm volatile("cp.async.wait_group 1;" ::: "memory");
        } else {
            asm volatile("cp.async.wait_group 0;" ::: "memory");
        }
        __syncthreads();            // all threads' copies for buf[step&1] visible

        const float* tb = tile[step & 1];

        u64 acc[4][3];
#pragma unroll
        for (int i = 0; i < 4; ++i)
#pragma unroll
            for (int r = 0; r < 3; ++r) acc[i][r] = 0ull;

#pragma unroll
        for (int kz = 0; kz < 3; ++kz) {
            const int zro = (kz == 0) ? zb0 : ((kz == 1) ? zb1 : zb2);
#pragma unroll
            for (int khy = 0; khy < 3; ++khy) {
                u64 wt[9];
#pragma unroll
                for (int j = 0; j < 9; ++j) wt[j] = uws2[kz * 27 + khy * 9 + j];
#pragma unroll
                for (int i = 0; i < 4; ++i) {       // output row h0s + i
                    const float* p = &tb[(zro + i + khy) * TW + w];
                    u64 v01 = *reinterpret_cast<const u64*>(p);
                    u64 v23 = *reinterpret_cast<const u64*>(p + 2);
                    float2 f01 = unpk(v01), f23 = unpk(v23);
                    u64 v12 = pack2(f01.y, f23.x);
                    fma2(acc[i][0], v01, wt[0]);
                    fma2(acc[i][1], v01, wt[1]);
                    fma2(acc[i][2], v01, wt[2]);
                    fma2(acc[i][0], v12, wt[3]);
                    fma2(acc[i][1], v12, wt[4]);
                    fma2(acc[i][2], v12, wt[5]);
                    fma2(acc[i][0], v23, wt[6]);
                    fma2(acc[i][1], v23, wt[7]);
                    fma2(acc[i][2], v23, wt[8]);
                }
            }
        }

        // ---- normalize over ranks, contract with Vp, store ----
#pragma unroll
        for (int i = 0; i < 4; ++i) {
            int sp = d * HW2 + (h0s + i) * 128 + w;
            float2 q0 = unpk(acc[i][0]), q1 = unpk(acc[i][1]), q2 = unpk(acc[i][2]);
            float2 w0 = *reinterpret_cast<const float2*>(vpb0 + sp);
            float2 w1 = *reinterpret_cast<const float2*>(vpb1 + sp);
            float2 w2 = *reinterpret_cast<const float2*>(vpb2 + sp);
            float sa = q0.x * q0.x + q1.x * q1.x + q2.x * q2.x;
            float sb = q0.y * q0.y + q1.y * q1.y + q2.y * q2.y;
            float ia = __fdividef(1.0f, 1e-6f + sqrtf(sa));
            float ib = __fdividef(1.0f, 1e-6f + sqrtf(sb));
            float oa = ia * (q0.x * w0.x + q1.x * w1.x + q2.x * w2.x);
            float ob = ib * (q0.y * w0.y + q1.y * w1.y + q2.y * w2.y);
            *reinterpret_cast<float2*>(UVc + sp) = make_float2(oa, ob);
        }
        __syncthreads();            // done reading buf[step&1] before refilling it
    }
#undef ISSUE_LOAD
}

// ---------------------------------------------------------------------------
extern "C" void kernel_launch(void* const* d_in, const int* in_sizes, int n_in,
                              void* d_out, int out_size) {
    const float* x      = (const float*)d_in[0];
    const float* head_w = (const float*)d_in[1];
    const float* tail_w = (const float*)d_in[2];
    const float* Uw     = (const float*)d_in[3];
    const float* Vw     = (const float*)d_in[4];
    float* out = (float*)d_out;

    dim3 gg(SPATIAL / 128, 2);
    wtranspose<<<1, 256>>>(head_w, tail_w);      // W -> g_wt (k-major)
    gemm_head<<<gg, 256>>>(x, Vw);               // h + Vp
    midkernel<<<dim3(8, 64, 2), 512>>>(Uw);      // UV (pipelined)
    gemm_tail<<<gg, 256>>>(out);                 // out
}

// round 14
// speedup vs baseline: 1.0822x; 1.0822x over previous
#include <cuda_runtime.h>
#include <cstdint>

#define SPATIAL 131072   // D*H*W per (batch, channel)
#define HW2     16384    // H*W
#define TW      136      // mid tile row stride (floats)

// Scratch (no allocations allowed anywhere)
__device__ float g_h [2 * 64 * SPATIAL];
__device__ float g_uv[2 * 64 * SPATIAL];
__device__ float g_vp[2 * 3  * SPATIAL];
__device__ float g_wt[2 * 4096];          // pre-transposed weights [k][m]

typedef unsigned long long u64;

__device__ __forceinline__ u64 pack_dup(float x) {
    u64 u; asm("mov.b64 %0, {%1, %2};" : "=l"(u) : "f"(x), "f"(x)); return u;
}
__device__ __forceinline__ u64 pack2(float a, float b) {
    u64 u; asm("mov.b64 %0, {%1, %2};" : "=l"(u) : "f"(a), "f"(b)); return u;
}
__device__ __forceinline__ void fma2(u64& d, u64 a, u64 b) {
    asm("fma.rn.f32x2 %0, %1, %2, %0;" : "+l"(d) : "l"(a), "l"(b));
}
__device__ __forceinline__ float2 unpk(u64 v) {
    float2 f; asm("mov.b64 {%0, %1}, %2;" : "=f"(f.x), "=f"(f.y) : "l"(v)); return f;
}

// ---------------------------------------------------------------------------
// One-time weight transpose: g_wt[sel][k*64+m] = W_sel[m*64+k]. 1 CTA.
// ---------------------------------------------------------------------------
__global__ void wtranspose(const float* __restrict__ hw,
                           const float* __restrict__ tw) {
    const int t = threadIdx.x;
#pragma unroll
    for (int i = 0; i < 16; ++i) {
        int idx = t + 256 * i;            // 0..4095
        int m = idx >> 6, k = idx & 63;
        g_wt[k * 64 + m]        = hw[idx];
        g_wt[4096 + k * 64 + m] = tw[idx];
    }
}

// ---------------------------------------------------------------------------
// f32x2 GEMM (R12, UNCHANGED — passed): C[b][m][p] = sum_k A[m][k]*X[b][k][p]
// CTA tile 64 x 128, 256 threads, thread tile 8m x 4n, 4 CTAs/SM.
// A fill = linear copy of pre-transposed g_wt (conflict-free).
// VP_EPI: Vp[b][r][p] = sum_m Vw[m][r] * C[m][p] (head only).
// ---------------------------------------------------------------------------
template<bool VP_EPI>
__device__ __forceinline__ void gemm_body(const float* __restrict__ X,
                                          const float* __restrict__ WT,
                                          float* __restrict__ C,
                                          const float* __restrict__ Vw) {
    __shared__ float As[64 * 64];    // [k][m], linear copy of WT
    __shared__ float Bs[64 * 128];   // [k][c]
    const int t  = threadIdx.x;
    const int b  = blockIdx.y;
    const int p0 = blockIdx.x * 128;
    const float* Xb = X + b * (64 * SPATIAL);

#pragma unroll
    for (int i = 0; i < 4; ++i) {            // A: straight 16KB copy
        int u = t + 256 * i;
        *reinterpret_cast<float4*>(As + u * 4) =
            *reinterpret_cast<const float4*>(WT + u * 4);
    }
#pragma unroll
    for (int i = 0; i < 8; ++i) {            // B tile 64 x 128 (2048 float4)
        int fl = t + 256 * i;
        int k = fl >> 5, cq = fl & 31;
        *reinterpret_cast<float4*>(Bs + k * 128 + cq * 4) =
            *reinterpret_cast<const float4*>(Xb + k * SPATIAL + p0 + cq * 4);
    }
    __syncthreads();

    const int cg = t & 31;      // cols cg*4 .. cg*4+3
    const int rg = t >> 5;      // rows rg*8 .. rg*8+7
    u64 acc[16];
#pragma unroll
    for (int i = 0; i < 16; ++i) acc[i] = 0ull;

#pragma unroll 8
    for (int k = 0; k < 64; ++k) {
        float4 a0 = *reinterpret_cast<const float4*>(As + k * 64 + rg * 8);
        float4 a1 = *reinterpret_cast<const float4*>(As + k * 64 + rg * 8 + 4);
        float4 bv = *reinterpret_cast<const float4*>(Bs + k * 128 + cg * 4);
        u64 bp0 = pack2(bv.x, bv.y), bp1 = pack2(bv.z, bv.w);
        float am[8] = {a0.x, a0.y, a0.z, a0.w, a1.x, a1.y, a1.z, a1.w};
#pragma unroll
        for (int j = 0; j < 8; ++j) {
            u64 aj = pack_dup(am[j]);
            fma2(acc[j * 2 + 0], aj, bp0);
            fma2(acc[j * 2 + 1], aj, bp1);
        }
    }

    float* Cb = C + b * (64 * SPATIAL);
#pragma unroll
    for (int j = 0; j < 8; ++j) {
        float2 lo = unpk(acc[j * 2 + 0]), hi = unpk(acc[j * 2 + 1]);
        *reinterpret_cast<float4*>(Cb + (rg * 8 + j) * SPATIAL + p0 + cg * 4)
            = make_float4(lo.x, lo.y, hi.x, hi.y);
    }

    if (VP_EPI) {
        u64 pvp[3][2];
#pragma unroll
        for (int r = 0; r < 3; ++r) { pvp[r][0] = 0ull; pvp[r][1] = 0ull; }
#pragma unroll
        for (int j = 0; j < 8; ++j) {
            int m = rg * 8 + j;
#pragma unroll
            for (int r = 0; r < 3; ++r) {
                u64 vw = pack_dup(__ldg(&Vw[m * 3 + r]));
                fma2(pvp[r][0], vw, acc[j * 2 + 0]);
                fma2(pvp[r][1], vw, acc[j * 2 + 1]);
            }
        }
        __syncthreads();                      // Bs reads done -> reuse as vred
        float* vred = Bs;                     // [rowg 8][r 3][col 128] = 12KB
#pragma unroll
        for (int r = 0; r < 3; ++r) {
            *reinterpret_cast<float2*>(vred + (rg * 3 + r) * 128 + cg * 4)     = unpk(pvp[r][0]);
            *reinterpret_cast<float2*>(vred + (rg * 3 + r) * 128 + cg * 4 + 2) = unpk(pvp[r][1]);
        }
        __syncthreads();
#pragma unroll
        for (int i = 0; i < 2; ++i) {
            int idx = t + 256 * i;            // 384 outputs
            if (idx < 384) {
                int r = idx >> 7, col = idx & 127;
                float s = 0.f;
#pragma unroll
                for (int g = 0; g < 8; ++g) s += vred[(g * 3 + r) * 128 + col];
                g_vp[(b * 3 + r) * SPATIAL + p0 + col] = s;
            }
        }
    }
}

// Non-templated entry points (templated __global__ silently no-ops under harness)
__global__ void __launch_bounds__(256, 4)
gemm_head(const float* __restrict__ X, const float* __restrict__ Vw) {
    gemm_body<true>(X, g_wt, g_h, Vw);
}
__global__ void __launch_bounds__(256, 4)
gemm_tail(float* __restrict__ C) {
    gemm_body<false>(g_uv, g_wt + 4096, C, nullptr);
}

// ---------------------------------------------------------------------------
// Fused middle (R7/R9/R11, UNCHANGED — best measured 86us): replicate-pad +
// depthwise 3x3x3 (3 ranks) + L2 norm + UV with precomputed Vp.
// CTA = 1 channel x all 8 d x 4 h-rows x 128 w. 512 threads, 2 CTAs/SM.
// ---------------------------------------------------------------------------
__global__ void __launch_bounds__(512, 2) midkernel(const float* __restrict__ Uw) {
    __shared__ __align__(16) float tile[8 * 6 * TW];   // [dz][hy 0..5][j], j = w+1
    __shared__ u64 uws2[81];
    const int t  = threadIdx.x;
    const int h0 = blockIdx.x * 4;
    const int c  = blockIdx.y;
    const int b  = blockIdx.z;
    const float* Hc = g_h + (b * 64 + c) * SPATIAL;

    if (t < 81) uws2[t] = pack_dup(Uw[t]);

    // ---- load halo tile: 48 rows (8 dz x 6 hy) x 130 floats ----
    {
        const int warp = t >> 5, lane = t & 31;
#pragma unroll
        for (int rr = 0; rr < 3; ++rr) {
            int row = warp + rr * 16;          // 0..47
            int dz = row / 6, hy = row - dz * 6;
            int gh = min(max(h0 + hy - 1, 0), 127);
            const float* src = Hc + dz * HW2 + gh * 128;
            float* dst = &tile[row * TW];
#pragma unroll
            for (int q = 0; q < 5; ++q) {
                int j = lane + q * 32;
                if (j < 130) dst[j] = src[min(max(j - 1, 0), 127)];
            }
        }
    }
    __syncthreads();

    const int d  = t >> 6;          // 0..7
    const int wp = t & 63;
    const int w  = wp * 2;          // output pair; tile j=w holds in[w-1]
    const int zb0 = max(d - 1, 0) * 6;
    const int zb1 = d * 6;
    const int zb2 = min(d + 1, 7) * 6;

    u64 acc[4][3];
#pragma unroll
    for (int i = 0; i < 4; ++i)
#pragma unroll
        for (int r = 0; r < 3; ++r) acc[i][r] = 0ull;

#pragma unroll
    for (int kz = 0; kz < 3; ++kz) {
        const int zro = (kz == 0) ? zb0 : ((kz == 1) ? zb1 : zb2);
#pragma unroll
        for (int khy = 0; khy < 3; ++khy) {
            u64 wt[9];
#pragma unroll
            for (int j = 0; j < 9; ++j) wt[j] = uws2[kz * 27 + khy * 9 + j];
#pragma unroll
            for (int i = 0; i < 4; ++i) {       // output row h0 + i
                const float* p = &tile[(zro + i + khy) * TW + w];
                u64 v01 = *reinterpret_cast<const u64*>(p);
                u64 v23 = *reinterpret_cast<const u64*>(p + 2);
                float2 f01 = unpk(v01), f23 = unpk(v23);
                u64 v12 = pack2(f01.y, f23.x);
                fma2(acc[i][0], v01, wt[0]);
                fma2(acc[i][1], v01, wt[1]);
                fma2(acc[i][2], v01, wt[2]);
                fma2(acc[i][0], v12, wt[3]);
                fma2(acc[i][1], v12, wt[4]);
                fma2(acc[i][2], v12, wt[5]);
                fma2(acc[i][0], v23, wt[6]);
                fma2(acc[i][1], v23, wt[7]);
                fma2(acc[i][2], v23, wt[8]);
            }
        }
    }

    // ---- normalize over ranks, contract with Vp, store ----
    float* UVc = g_uv + (b * 64 + c) * SPATIAL;
    const float* vpb0 = g_vp + (b * 3 + 0) * SPATIAL;
    const float* vpb1 = g_vp + (b * 3 + 1) * SPATIAL;
    const float* vpb2 = g_vp + (b * 3 + 2) * SPATIAL;
#pragma unroll
    for (int i = 0; i < 4; ++i) {
        int sp = d * HW2 + (h0 + i) * 128 + w;
        float2 q0 = unpk(acc[i][0]), q1 = unpk(acc[i][1]), q2 = unpk(acc[i][2]);
        float2 w0 = *reinterpret_cast<const float2*>(vpb0 + sp);
        float2 w1 = *reinterpret_cast<const float2*>(vpb1 + sp);
        float2 w2 = *reinterpret_cast<const float2*>(vpb2 + sp);
        float sa = q0.x * q0.x + q1.x * q1.x + q2.x * q2.x;
        float sb = q0.y * q0.y + q1.y * q1.y + q2.y * q2.y;
        float ia = __fdividef(1.0f, 1e-6f + sqrtf(sa));
        float ib = __fdividef(1.0f, 1e-6f + sqrtf(sb));
        float oa = ia * (q0.x * w0.x + q1.x * w1.x + q2.x * w2.x);
        float ob = ib * (q0.y * w0.y + q1.y * w1.y + q2.y * w2.y);
        *reinterpret_cast<float2*>(UVc + sp) = make_float2(oa, ob);
    }
}

// ---------------------------------------------------------------------------
extern "C" void kernel_launch(void* const* d_in, const int* in_sizes, int n_in,
                              void* d_out, int out_size) {
    const float* x      = (const float*)d_in[0];
    const float* head_w = (const float*)d_in[1];
    const float* tail_w = (const float*)d_in[2];
    const float* Uw     = (const float*)d_in[3];
    const float* Vw     = (const float*)d_in[4];
    float* out = (float*)d_out;

    dim3 gg(SPATIAL / 128, 2);
    wtranspose<<<1, 256>>>(head_w, tail_w);      // W -> g_wt (k-major)
    gemm_head<<<gg, 256>>>(x, Vw);               // h + Vp
    midkernel<<<dim3(32, 64, 2), 512>>>(Uw);     // UV
    gemm_tail<<<gg, 256>>>(out);                 // out
}